// round 5
// baseline (speedup 1.0000x reference)
#include <cuda_runtime.h>

// SinkhornScorer fused kernel for GB300 (sm_103a).
// R5: TWO batch elements per CTA. Sinkhorn iterations for both batches share
// barriers (2/iter instead of 3, serving 2 batches); dustbin scaling a64 is
// computed redundantly per-warp to kill one barrier; GEMMs sequential with
// 32-k staging chunks + register-prefetch double buffering; FFMA2 throughout.

namespace {
constexpr int H   = 256;
constexpr int NN  = 64;
constexpr int NP  = 65;
constexpr float LOG128 = 4.852030263919617f;
constexpr float MU_IN  = 0.0078125f;   // 1/128
constexpr float MU_DB  = 0.5f;         // 64/128

__device__ __forceinline__ float warp_sum(float v) {
#pragma unroll
    for (int o = 16; o; o >>= 1) v += __shfl_xor_sync(0xffffffffu, v, o);
    return v;
}
__device__ __forceinline__ unsigned long long ffma2(
    unsigned long long a, unsigned long long b, unsigned long long c) {
    unsigned long long d;
    asm("fma.rn.f32x2 %0, %1, %2, %3;" : "=l"(d) : "l"(a), "l"(b), "l"(c));
    return d;
}
__device__ __forceinline__ unsigned long long fmul2(
    unsigned long long a, unsigned long long b) {
    unsigned long long d;
    asm("mul.rn.f32x2 %0, %1, %2;" : "=l"(d) : "l"(a), "l"(b));
    return d;
}
__device__ __forceinline__ unsigned long long pack2(float lo, float hi) {
    unsigned long long d;
    asm("mov.b64 %0, {%1, %2};" : "=l"(d) : "f"(lo), "f"(hi));
    return d;
}
__device__ __forceinline__ void unpack2(unsigned long long v, float& lo, float& hi) {
    asm("mov.b64 {%0, %1}, %2;" : "=f"(lo), "=f"(hi) : "l"(v));
}
__device__ __forceinline__ float pairsum(unsigned long long v) {
    float lo, hi; unpack2(v, lo, hi); return lo + hi;
}

// Fold 8 per-lane row-partials into one full row sum; lane ends owning row
// (lane>>2)&7 (value replicated in each lane group of 4).
__device__ __forceinline__ float collapse8(const float* s, int lane) {
    const bool b4 = (lane & 16) != 0;
    const bool b3 = (lane & 8)  != 0;
    const bool bq = (lane & 4)  != 0;
    float t0, t1, t2, t3;
    t0 = __shfl_xor_sync(0xffffffffu, b4 ? s[0] : s[4], 16);
    t1 = __shfl_xor_sync(0xffffffffu, b4 ? s[1] : s[5], 16);
    t2 = __shfl_xor_sync(0xffffffffu, b4 ? s[2] : s[6], 16);
    t3 = __shfl_xor_sync(0xffffffffu, b4 ? s[3] : s[7], 16);
    float u0 = (b4 ? s[4] : s[0]) + t0;
    float u1 = (b4 ? s[5] : s[1]) + t1;
    float u2 = (b4 ? s[6] : s[2]) + t2;
    float u3 = (b4 ? s[7] : s[3]) + t3;
    t0 = __shfl_xor_sync(0xffffffffu, b3 ? u0 : u2, 8);
    t1 = __shfl_xor_sync(0xffffffffu, b3 ? u1 : u3, 8);
    float w0 = (b3 ? u2 : u0) + t0;
    float w1 = (b3 ? u3 : u1) + t1;
    t0 = __shfl_xor_sync(0xffffffffu, bq ? w0 : w1, 4);
    float z = (bq ? w1 : w0) + t0;
    z += __shfl_xor_sync(0xffffffffu, z, 2);
    z += __shfl_xor_sync(0xffffffffu, z, 1);
    return z;
}
}  // namespace

__global__ void __launch_bounds__(256, 3) sinkhorn_fused_kernel(
    const float* __restrict__ x, const float* __restrict__ y,
    const float* __restrict__ gamma, const float* __restrict__ beta,
    const float* __restrict__ wdb, const float* __restrict__ bdb,
    float* __restrict__ out_match, float* __restrict__ out_score,
    int write_score)
{
    const int bA   = blockIdx.x * 2;
    const int bB   = bA + 1;
    const int t    = threadIdx.x;
    const int lane = t & 31;
    const int wid  = t >> 5;
    const int w8   = wid * 8;
    const int c0   = lane;
    const int c1   = lane + 32;
    const int rl   = (lane >> 2) & 7;

    __shared__ __align__(16) float sCA[4240];   // C for batch A (65x65)
    __shared__ __align__(16) float sCB[4240];   // C for batch B; staging overlay
    __shared__ __align__(16) float sGw[256];
    __shared__ float sScale[256];               // xA|yA|xB|yB
    __shared__ float sAlpha[256];
    __shared__ float sBvA[NP], sBvB[NP];
    __shared__ float sKdbRowA[NP], sKdbRowB[NP], sKdbColA[NP], sKdbColB[NP];
    __shared__ float sPartA[8 * 66], sPartB[8 * 66];
    __shared__ float sAfinA[NP], sAfinB[NP], sLaA[NP], sLaB[NP], sLbA[NP], sLbB[NP];
    __shared__ float sRed[16];
    __shared__ float sSgw, sSbw;

    // ---- constants ----
    {
        float gwv = gamma[t] * wdb[t];
        float bwv = beta[t] * wdb[t];
        sGw[t] = gwv;
        gwv = warp_sum(gwv);
        bwv = warp_sum(bwv);
        if (lane == 0) { sRed[wid] = gwv; sRed[8 + wid] = bwv; }
    }
    __syncthreads();
    if (t == 0) {
        float a = 0.f, c = 0.f;
#pragma unroll
        for (int i = 0; i < 8; i++) { a += sRed[i]; c += sRed[8 + i]; }
        sSgw = a;
        sSbw = c + bdb[0];
    }
    __syncthreads();

    const float* xbA = x + (size_t)bA * NN * H;
    const float* ybA = y + (size_t)bA * NN * H;
    const float* xbB = x + (size_t)bB * NN * H;
    const float* ybB = y + (size_t)bB * NN * H;

    // ---- Phase A: per-row stats, 256 rows (xA|yA|xB|yB), one warp per row ----
    {
        const float4* gw4 = (const float4*)sGw;
        for (int rr = wid; rr < 256; rr += 8) {
            const float* rp;
            if      (rr < 64)  rp = xbA + rr * H;
            else if (rr < 128) rp = ybA + (rr - 64) * H;
            else if (rr < 192) rp = xbB + (rr - 128) * H;
            else               rp = ybB + (rr - 192) * H;
            const float4* rp4 = (const float4*)rp;
            float s1 = 0.f, s2 = 0.f, s3 = 0.f;
#pragma unroll
            for (int qq = 0; qq < 2; qq++) {
                float4 v = rp4[lane + 32 * qq];
                float4 g = gw4[lane + 32 * qq];
                s1 += (v.x + v.y) + (v.z + v.w);
                s2 += v.x * v.x + v.y * v.y + v.z * v.z + v.w * v.w;
                s3 += v.x * g.x + v.y * g.y + v.z * g.z + v.w * g.w;
            }
            s1 = warp_sum(s1);
            s2 = warp_sum(s2);
            s3 = warp_sum(s3);
            if (lane == 0) {
                sScale[rr] = 1.0f / fmaxf(sqrtf(s2), 1e-12f);
                float mu      = s1 * (1.0f / 256.0f);
                float var     = s2 * (1.0f / 256.0f) - mu * mu;
                float inv_std = rsqrtf(var + 1e-5f);
                sAlpha[rr] = tanhf(inv_std * (s3 - mu * sSgw) + sSbw);
            }
        }
    }

    // ---- GEMM helper state: staging overlays sCB (4096 floats used) ----
    float4* xs4 = (float4*)sCB;            // [64][8] float4, swizzled
    float4* ys4 = ((float4*)sCB) + 512;
    const ulonglong2* xs2 = (const ulonglong2*)xs4;
    const ulonglong2* ys2 = (const ulonglong2*)ys4;

    unsigned long long kreg2A[8], kreg2B[8];

#define DO_GEMM(XG, YG, ACC)                                                   \
    {                                                                          \
        const float4* xg = (const float4*)(XG);                                \
        const float4* yg = (const float4*)(YG);                                \
        float4 px[2], py[2];                                                   \
        _Pragma("unroll")                                                      \
        for (int qq = 0; qq < 2; qq++) {                                       \
            int idx = t + 256 * qq;                                            \
            int row = idx >> 3, c4 = idx & 7;                                  \
            px[qq] = xg[row * 64 + c4];                                        \
            py[qq] = yg[row * 64 + c4];                                        \
        }                                                                      \
        for (int kc = 0; kc < 8; kc++) {                                       \
            __syncthreads();                                                   \
            _Pragma("unroll")                                                  \
            for (int qq = 0; qq < 2; qq++) {                                   \
                int idx = t + 256 * qq;                                        \
                int row = idx >> 3, c4 = idx & 7;                              \
                int sw = c4 ^ (row & 7);                                       \
                xs4[row * 8 + sw] = px[qq];                                    \
                ys4[row * 8 + sw] = py[qq];                                    \
            }                                                                  \
            __syncthreads();                                                   \
            if (kc < 7) {                                                      \
                _Pragma("unroll")                                              \
                for (int qq = 0; qq < 2; qq++) {                               \
                    int idx = t + 256 * qq;                                    \
                    int row = idx >> 3, c4 = idx & 7;                          \
                    px[qq] = xg[row * 64 + (kc + 1) * 8 + c4];                 \
                    py[qq] = yg[row * 64 + (kc + 1) * 8 + c4];                 \
                }                                                              \
            }                                                                  \
            _Pragma("unroll")                                                  \
            for (int k4 = 0; k4 < 8; k4++) {                                   \
                ulonglong2 yv0 = ys2[c0 * 8 + (k4 ^ (c0 & 7))];                \
                ulonglong2 yv1 = ys2[c1 * 8 + (k4 ^ (c1 & 7))];                \
                _Pragma("unroll")                                              \
                for (int r = 0; r < 8; r++) {                                  \
                    ulonglong2 xv = xs2[(w8 + r) * 8 + (k4 ^ r)];              \
                    ACC[r][0] = ffma2(xv.x, yv0.x, ACC[r][0]);                 \
                    ACC[r][0] = ffma2(xv.y, yv0.y, ACC[r][0]);                 \
                    ACC[r][1] = ffma2(xv.x, yv1.x, ACC[r][1]);                 \
                    ACC[r][1] = ffma2(xv.y, yv1.y, ACC[r][1]);                 \
                }                                                              \
            }                                                                  \
        }                                                                      \
    }

    // ---- GEMM + C for batch A (kreg regenerated later) ----
    {
        unsigned long long acc2[8][2];
#pragma unroll
        for (int r = 0; r < 8; r++) { acc2[r][0] = 0ull; acc2[r][1] = 0ull; }
        DO_GEMM(xbA, ybA, acc2);
        const float sj0 = sScale[64 + c0] * 10.0f;
        const float sj1 = sScale[64 + c1] * 10.0f;
#pragma unroll
        for (int r = 0; r < 8; r++) {
            float si = sScale[w8 + r];
            sCA[(w8 + r) * NP + c0] = pairsum(acc2[r][0]) * si * sj0;
            sCA[(w8 + r) * NP + c1] = pairsum(acc2[r][1]) * si * sj1;
        }
    }
    // ---- GEMM + C for batch B (kreg2B computed directly) ----
    {
        unsigned long long acc2[8][2];
#pragma unroll
        for (int r = 0; r < 8; r++) { acc2[r][0] = 0ull; acc2[r][1] = 0ull; }
        DO_GEMM(xbB, ybB, acc2);
        __syncthreads();   // all staging reads done before overlaying with C_B
        const float sj0 = sScale[192 + c0] * 10.0f;
        const float sj1 = sScale[192 + c1] * 10.0f;
#pragma unroll
        for (int r = 0; r < 8; r++) {
            float si  = sScale[128 + w8 + r];
            float cv0 = pairsum(acc2[r][0]) * si * sj0;
            float cv1 = pairsum(acc2[r][1]) * si * sj1;
            sCB[(w8 + r) * NP + c0] = cv0;
            sCB[(w8 + r) * NP + c1] = cv1;
            kreg2B[r] = pack2(__expf(cv0), __expf(cv1));
        }
    }
    // kreg2A regenerated from C_A (same cells this thread wrote)
#pragma unroll
    for (int r = 0; r < 8; r++)
        kreg2A[r] = pack2(__expf(sCA[(w8 + r) * NP + c0]),
                          __expf(sCA[(w8 + r) * NP + c1]));

    // ---- dustbins, corners, b init ----
    if (t < 64) {
        float cx = 10.0f * sAlpha[t];
        sCA[t * NP + 64] = cx;  sKdbColA[t] = __expf(cx);
        float cy = 10.0f * sAlpha[64 + t];
        sCA[64 * NP + t] = cy;  sKdbRowA[t] = __expf(cy);
        float dx = 10.0f * sAlpha[128 + t];
        sCB[t * NP + 64] = dx;  sKdbColB[t] = __expf(dx);
        float dy = 10.0f * sAlpha[192 + t];
        sCB[64 * NP + t] = dy;  sKdbRowB[t] = __expf(dy);
    }
    if (t == 0) {
        sCA[64 * NP + 64] = -1000.0f;  sKdbRowA[64] = 0.0f;  sKdbColA[64] = 0.0f;
        sCB[64 * NP + 64] = -1000.0f;  sKdbRowB[64] = 0.0f;  sKdbColB[64] = 0.0f;
    }
    if (t < NP) sBvA[t] = 1.0f;
    if (t >= 128 && t < 128 + NP) sBvB[t - 128] = 1.0f;
    __syncthreads();

    // ---- Sinkhorn: 20 iterations, both batches, 2 barriers/iter ----
    float rcpA = 0.f, rcpB = 0.f, a64A = 0.f, a64B = 0.f;
    const float kColA = sKdbColA[w8 + rl];   // constant across iters
    const float kColB = sKdbColB[w8 + rl];

    for (int it = 0; it < 20; it++) {
        // ---- u-phase (no barrier needed after; a64 redundant per warp) ----
        float bA0 = sBvA[c0], bA1 = sBvA[c1], bA64 = sBvA[64];
        float bB0 = sBvB[c0], bB1 = sBvB[c1], bB64 = sBvB[64];
        {
            unsigned long long b2 = pack2(bA0, bA1);
            float s[8];
#pragma unroll
            for (int r = 0; r < 8; r++) s[r] = pairsum(fmul2(kreg2A[r], b2));
            float z = collapse8(s, lane);
            z = fmaf(kColA, bA64, z);
            rcpA = __fdividef(MU_IN, z);
            float pdb = fmaf(sKdbRowA[c0], bA0, sKdbRowA[c1] * bA1);
            a64A = __fdividef(MU_DB, warp_sum(pdb));
        }
        {
            unsigned long long b2 = pack2(bB0, bB1);
            float s[8];
#pragma unroll
            for (int r = 0; r < 8; r++) s[r] = pairsum(fmul2(kreg2B[r], b2));
            float z = collapse8(s, lane);
            z = fmaf(kColB, bB64, z);
            rcpB = __fdividef(MU_IN, z);
            float pdb = fmaf(sKdbRowB[c0], bB0, sKdbRowB[c1] * bB1);
            a64B = __fdividef(MU_DB, warp_sum(pdb));
        }
        // ---- v-phase partials ----
        {
            unsigned long long q2 = 0ull;
            float qdb = 0.f;
#pragma unroll
            for (int r = 0; r < 8; r++) {
                float ar = __shfl_sync(0xffffffffu, rcpA, r * 4);
                q2  = ffma2(kreg2A[r], pack2(ar, ar), q2);
                qdb = fmaf(sKdbColA[w8 + r], ar, qdb);
            }
            float q0, q1; unpack2(q2, q0, q1);
            sPartA[wid * 66 + c0] = q0;
            sPartA[wid * 66 + c1] = q1;
            if (lane == 0) sPartA[wid * 66 + 64] = qdb;
        }
        {
            unsigned long long q2 = 0ull;
            float qdb = 0.f;
#pragma unroll
            for (int r = 0; r < 8; r++) {
                float ar = __shfl_sync(0xffffffffu, rcpB, r * 4);
                q2  = ffma2(kreg2B[r], pack2(ar, ar), q2);
                qdb = fmaf(sKdbColB[w8 + r], ar, qdb);
            }
            float q0, q1; unpack2(q2, q0, q1);
            sPartB[wid * 66 + c0] = q0;
            sPartB[wid * 66 + c1] = q1;
            if (lane == 0) sPartB[wid * 66 + 64] = qdb;
        }
        __syncthreads();
        // ---- b update: warps 0-2 do A, warps 4-6 do B ----
        if (t < NP) {
            float cs = 0.f;
#pragma unroll
            for (int w = 0; w < 8; w++) cs += sPartA[w * 66 + t];
            sBvA[t] = (t < 64) ? __fdividef(MU_IN, fmaf(sKdbRowA[t], a64A, cs))
                               : __fdividef(MU_DB, cs);
        }
        if (t >= 128 && t < 128 + NP) {
            int tt = t - 128;
            float cs = 0.f;
#pragma unroll
            for (int w = 0; w < 8; w++) cs += sPartB[w * 66 + tt];
            sBvB[tt] = (tt < 64) ? __fdividef(MU_IN, fmaf(sKdbRowB[tt], a64B, cs))
                                 : __fdividef(MU_DB, cs);
        }
        __syncthreads();
    }

    // ---- Epilogue ----
    if ((lane & 3) == 0) { sAfinA[w8 + rl] = rcpA; sAfinB[w8 + rl] = rcpB; }
    if (t == 0) { sAfinA[64] = a64A; sAfinB[64] = a64B; }
    __syncthreads();
    if (t < NP) { sLaA[t] = __logf(sAfinA[t]); sLbA[t] = __logf(sBvA[t]); }
    if (t >= 128 && t < 128 + NP) {
        int tt = t - 128;
        sLaB[tt] = __logf(sAfinB[tt]); sLbB[tt] = __logf(sBvB[tt]);
    }
    __syncthreads();

    float* omA = out_match + (size_t)bA * (NP * NP);
    float* omB = out_match + (size_t)bB * (NP * NP);
    for (int i = wid; i < NP; i += 8) {
        float laA = sLaA[i] + LOG128;
        float laB = sLaB[i] + LOG128;
        const float* CiA = sCA + i * NP;
        const float* CiB = sCB + i * NP;
        float* oA = omA + i * NP;
        float* oB = omB + i * NP;
        for (int j = lane; j < NP; j += 32) {
            oA[j] = CiA[j] + laA + sLbA[j];
            oB[j] = CiB[j] + laB + sLbB[j];
        }
    }

    if (write_score) {
        float pA = 0.f, pB = 0.f;
        float bbA0 = sBvA[c0], bbA1 = sBvA[c1];
        float bbB0 = sBvB[c0], bbB1 = sBvB[c1];
#pragma unroll
        for (int r = 0; r < 8; r++) {
            float arA = __shfl_sync(0xffffffffu, rcpA, r * 4);
            float arB = __shfl_sync(0xffffffffu, rcpB, r * 4);
            float k0, k1;
            unpack2(kreg2A[r], k0, k1);
            pA += arA * (k0 * sCA[(w8 + r) * NP + c0] * bbA0 +
                         k1 * sCA[(w8 + r) * NP + c1] * bbA1);
            unpack2(kreg2B[r], k0, k1);
            pB += arB * (k0 * sCB[(w8 + r) * NP + c0] * bbB0 +
                         k1 * sCB[(w8 + r) * NP + c1] * bbB1);
        }
        pA = warp_sum(pA);
        pB = warp_sum(pB);
        if (lane == 0) { sRed[wid] = pA; sRed[8 + wid] = pB; }
        __syncthreads();
        if (t == 0) {
            float sa = 0.f, sb = 0.f;
#pragma unroll
            for (int i = 0; i < 8; i++) { sa += sRed[i]; sb += sRed[8 + i]; }
            out_score[bA] = sa * 128.0f;
            out_score[bB] = sb * 128.0f;
        }
    }
#undef DO_GEMM
}

extern "C" void kernel_launch(void* const* d_in, const int* in_sizes, int n_in,
                              void* d_out, int out_size) {
    const float* x     = (const float*)d_in[0];
    const float* y     = (const float*)d_in[1];
    const float* gamma = (const float*)d_in[2];
    const float* beta  = (const float*)d_in[3];
    const float* wdb   = (const float*)d_in[4];
    const float* bdb   = (const float*)d_in[5];

    int B = in_sizes[0] / (NN * H);                 // 4096 (even)
    size_t msz = (size_t)B * NP * NP;
    float* out_match = (float*)d_out;
    float* out_score = (float*)d_out + msz;
    int write_score = ((size_t)out_size >= msz + (size_t)B) ? 1 : 0;

    sinkhorn_fused_kernel<<<B / 2, 256>>>(x, y, gamma, beta, wdb, bdb,
                                          out_match, out_score, write_score);
}

// round 6
// speedup vs baseline: 1.1840x; 1.1840x over previous
#include <cuda_runtime.h>

// SinkhornScorer fused kernel for GB300 (sm_103a).
// R6: stats fused into GEMM staging (phase A deleted, DRAM halved),
// dustbin scalings computed by dedicated warps (3 -> A, 7 -> B),
// two batches per CTA, FFMA2 GEMM + register-resident K, 2 barriers/iter.

namespace {
constexpr int H   = 256;
constexpr int NN  = 64;
constexpr int NP  = 65;
constexpr float LOG128 = 4.852030263919617f;
constexpr float MU_IN  = 0.0078125f;   // 1/128
constexpr float MU_DB  = 0.5f;         // 64/128

__device__ __forceinline__ float warp_sum(float v) {
#pragma unroll
    for (int o = 16; o; o >>= 1) v += __shfl_xor_sync(0xffffffffu, v, o);
    return v;
}
__device__ __forceinline__ unsigned long long ffma2(
    unsigned long long a, unsigned long long b, unsigned long long c) {
    unsigned long long d;
    asm("fma.rn.f32x2 %0, %1, %2, %3;" : "=l"(d) : "l"(a), "l"(b), "l"(c));
    return d;
}
__device__ __forceinline__ unsigned long long fmul2(
    unsigned long long a, unsigned long long b) {
    unsigned long long d;
    asm("mul.rn.f32x2 %0, %1, %2;" : "=l"(d) : "l"(a), "l"(b));
    return d;
}
__device__ __forceinline__ unsigned long long pack2(float lo, float hi) {
    unsigned long long d;
    asm("mov.b64 %0, {%1, %2};" : "=l"(d) : "f"(lo), "f"(hi));
    return d;
}
__device__ __forceinline__ void unpack2(unsigned long long v, float& lo, float& hi) {
    asm("mov.b64 {%0, %1}, %2;" : "=f"(lo), "=f"(hi) : "l"(v));
}
__device__ __forceinline__ float pairsum(unsigned long long v) {
    float lo, hi; unpack2(v, lo, hi); return lo + hi;
}

// Fold 8 per-lane row-partials into one row sum; lane ends owning row
// (lane>>2)&7, value replicated within each 4-lane group.
__device__ __forceinline__ float collapse8(const float* s, int lane) {
    const bool b4 = (lane & 16) != 0;
    const bool b3 = (lane & 8)  != 0;
    const bool bq = (lane & 4)  != 0;
    float t0, t1, t2, t3;
    t0 = __shfl_xor_sync(0xffffffffu, b4 ? s[0] : s[4], 16);
    t1 = __shfl_xor_sync(0xffffffffu, b4 ? s[1] : s[5], 16);
    t2 = __shfl_xor_sync(0xffffffffu, b4 ? s[2] : s[6], 16);
    t3 = __shfl_xor_sync(0xffffffffu, b4 ? s[3] : s[7], 16);
    float u0 = (b4 ? s[4] : s[0]) + t0;
    float u1 = (b4 ? s[5] : s[1]) + t1;
    float u2 = (b4 ? s[6] : s[2]) + t2;
    float u3 = (b4 ? s[7] : s[3]) + t3;
    t0 = __shfl_xor_sync(0xffffffffu, b3 ? u0 : u2, 8);
    t1 = __shfl_xor_sync(0xffffffffu, b3 ? u1 : u3, 8);
    float w0 = (b3 ? u2 : u0) + t0;
    float w1 = (b3 ? u3 : u1) + t1;
    t0 = __shfl_xor_sync(0xffffffffu, bq ? w0 : w1, 4);
    float z = (bq ? w1 : w0) + t0;
    z += __shfl_xor_sync(0xffffffffu, z, 2);
    z += __shfl_xor_sync(0xffffffffu, z, 1);
    return z;
}
}  // namespace

__global__ void __launch_bounds__(256, 3) sinkhorn_fused_kernel(
    const float* __restrict__ x, const float* __restrict__ y,
    const float* __restrict__ gamma, const float* __restrict__ beta,
    const float* __restrict__ wdb, const float* __restrict__ bdb,
    float* __restrict__ out_match, float* __restrict__ out_score,
    int write_score)
{
    const int bA   = blockIdx.x * 2;
    const int bB   = bA + 1;
    const int t    = threadIdx.x;
    const int lane = t & 31;
    const int wid  = t >> 5;
    const int w8   = wid * 8;
    const int c0   = lane;
    const int c1   = lane + 32;
    const int rl   = (lane >> 2) & 7;

    __shared__ __align__(16) float sCA[4240];   // C for batch A
    __shared__ __align__(16) float sCB[4240];   // C for batch B; staging overlay
    __shared__ __align__(16) float sGw[256];
    __shared__ float sScale[256];               // xA|yA|xB|yB
    __shared__ float sAlpha[256];
    __shared__ float sBvA[NP], sBvB[NP];
    __shared__ float sKdbRowA[NP], sKdbRowB[NP], sKdbColA[NP], sKdbColB[NP];
    __shared__ float sPartA[8 * 66], sPartB[8 * 66];
    __shared__ float sAfinA[NP], sAfinB[NP], sLaA[NP], sLaB[NP], sLbA[NP], sLbB[NP];
    __shared__ float sRed[16];
    __shared__ float sSgw, sSbw, sA64A, sA64B;

    // ---- constants: gw = gamma*w; S_gw = sum gw; S_bw = sum beta*w + b_db ----
    {
        float gwv = gamma[t] * wdb[t];
        float bwv = beta[t] * wdb[t];
        sGw[t] = gwv;
        gwv = warp_sum(gwv);
        bwv = warp_sum(bwv);
        if (lane == 0) { sRed[wid] = gwv; sRed[8 + wid] = bwv; }
    }
    __syncthreads();
    if (t == 0) {
        float a = 0.f, c = 0.f;
#pragma unroll
        for (int i = 0; i < 8; i++) { a += sRed[i]; c += sRed[8 + i]; }
        sSgw = a;
        sSbw = c + bdb[0];
    }
    __syncthreads();

    const float* xbA = x + (size_t)bA * NN * H;
    const float* ybA = y + (size_t)bA * NN * H;
    const float* xbB = x + (size_t)bB * NN * H;
    const float* ybB = y + (size_t)bB * NN * H;

    // Staging overlays sCB (4096 floats used)
    float4* xs4 = (float4*)sCB;            // [64][8] float4, swizzled
    float4* ys4 = ((float4*)sCB) + 512;
    const ulonglong2* xs2 = (const ulonglong2*)xs4;
    const ulonglong2* ys2 = (const ulonglong2*)ys4;
    const float4* gw4 = (const float4*)sGw;

    unsigned long long kreg2A[8], kreg2B[8];

    // per-thread row-stat accumulators (rows t>>3 and t>>3+32 of x and y)
    float st_x1[2], st_x2[2], st_x3[2], st_y1[2], st_y2[2], st_y3[2];

#define STAT_CLEAR()                                                           \
    _Pragma("unroll")                                                          \
    for (int qq = 0; qq < 2; qq++) {                                           \
        st_x1[qq] = 0.f; st_x2[qq] = 0.f; st_x3[qq] = 0.f;                     \
        st_y1[qq] = 0.f; st_y2[qq] = 0.f; st_y3[qq] = 0.f;                     \
    }

#define STAT_ACC(GQ)                                                           \
    _Pragma("unroll")                                                          \
    for (int qq = 0; qq < 2; qq++) {                                           \
        float4 v = px[qq];                                                     \
        st_x1[qq] += (v.x + v.y) + (v.z + v.w);                                \
        st_x2[qq] += v.x * v.x + v.y * v.y + v.z * v.z + v.w * v.w;            \
        st_x3[qq] += v.x * (GQ).x + v.y * (GQ).y + v.z * (GQ).z + v.w * (GQ).w;\
        float4 u = py[qq];                                                     \
        st_y1[qq] += (u.x + u.y) + (u.z + u.w);                                \
        st_y2[qq] += u.x * u.x + u.y * u.y + u.z * u.z + u.w * u.w;            \
        st_y3[qq] += u.x * (GQ).x + u.y * (GQ).y + u.z * (GQ).z + u.w * (GQ).w;\
    }

#define DO_GEMM(XG, YG, ACC)                                                   \
    {                                                                          \
        const float4* xg = (const float4*)(XG);                                \
        const float4* yg = (const float4*)(YG);                                \
        const int srow = t >> 3, sc4 = t & 7;                                  \
        float4 px[2], py[2];                                                   \
        px[0] = xg[srow * 64 + sc4];                                           \
        px[1] = xg[(srow + 32) * 64 + sc4];                                    \
        py[0] = yg[srow * 64 + sc4];                                           \
        py[1] = yg[(srow + 32) * 64 + sc4];                                    \
        {                                                                      \
            float4 gq = gw4[sc4];                                              \
            STAT_ACC(gq);                                                      \
        }                                                                      \
        for (int kc = 0; kc < 8; kc++) {                                       \
            __syncthreads();                                                   \
            {                                                                  \
                int sw0 = sc4 ^ (srow & 7);                                    \
                xs4[srow * 8 + sw0] = px[0];                                   \
                ys4[srow * 8 + sw0] = py[0];                                   \
                xs4[(srow + 32) * 8 + sw0] = px[1];                            \
                ys4[(srow + 32) * 8 + sw0] = py[1];                            \
            }                                                                  \
            __syncthreads();                                                   \
            if (kc < 7) {                                                      \
                int col = (kc + 1) * 8 + sc4;                                  \
                px[0] = xg[srow * 64 + col];                                   \
                px[1] = xg[(srow + 32) * 64 + col];                            \
                py[0] = yg[srow * 64 + col];                                   \
                py[1] = yg[(srow + 32) * 64 + col];                            \
                float4 gq = gw4[col];                                          \
                STAT_ACC(gq);                                                  \
            }                                                                  \
            _Pragma("unroll")                                                  \
            for (int k4 = 0; k4 < 8; k4++) {                                   \
                ulonglong2 yv0 = ys2[c0 * 8 + (k4 ^ (c0 & 7))];                \
                ulonglong2 yv1 = ys2[c1 * 8 + (k4 ^ (c1 & 7))];                \
                _Pragma("unroll")                                              \
                for (int r = 0; r < 8; r++) {                                  \
                    ulonglong2 xv = xs2[(w8 + r) * 8 + (k4 ^ r)];              \
                    ACC[r][0] = ffma2(xv.x, yv0.x, ACC[r][0]);                 \
                    ACC[r][0] = ffma2(xv.y, yv0.y, ACC[r][0]);                 \
                    ACC[r][1] = ffma2(xv.x, yv1.x, ACC[r][1]);                 \
                    ACC[r][1] = ffma2(xv.y, yv1.y, ACC[r][1]);                 \
                }                                                              \
            }                                                                  \
        }                                                                      \
    }

    // Reduce stats over 8-lane groups and write scale/alpha for one batch.
    // base = 0 for batch A, 128 for batch B.
#define STAT_WRITE(BASE)                                                       \
    {                                                                          \
        _Pragma("unroll")                                                      \
        for (int o = 1; o <= 4; o <<= 1) {                                     \
            _Pragma("unroll")                                                  \
            for (int qq = 0; qq < 2; qq++) {                                   \
                st_x1[qq] += __shfl_xor_sync(0xffffffffu, st_x1[qq], o);       \
                st_x2[qq] += __shfl_xor_sync(0xffffffffu, st_x2[qq], o);       \
                st_x3[qq] += __shfl_xor_sync(0xffffffffu, st_x3[qq], o);       \
                st_y1[qq] += __shfl_xor_sync(0xffffffffu, st_y1[qq], o);       \
                st_y2[qq] += __shfl_xor_sync(0xffffffffu, st_y2[qq], o);       \
                st_y3[qq] += __shfl_xor_sync(0xffffffffu, st_y3[qq], o);       \
            }                                                                  \
        }                                                                      \
        if ((lane & 7) == 0) {                                                 \
            int row = wid * 4 + (lane >> 3);                                   \
            float Sgw = sSgw, Sbw = sSbw;                                      \
            _Pragma("unroll")                                                  \
            for (int qq = 0; qq < 2; qq++) {                                   \
                int rx = (BASE) + row + 32 * qq;                               \
                sScale[rx] = 1.0f / fmaxf(sqrtf(st_x2[qq]), 1e-12f);           \
                float mu  = st_x1[qq] * (1.0f / 256.0f);                       \
                float var = st_x2[qq] * (1.0f / 256.0f) - mu * mu;             \
                sAlpha[rx] = tanhf(rsqrtf(var + 1e-5f) *                       \
                                   (st_x3[qq] - mu * Sgw) + Sbw);              \
                int ry = (BASE) + 64 + row + 32 * qq;                          \
                sScale[ry] = 1.0f / fmaxf(sqrtf(st_y2[qq]), 1e-12f);           \
                float muy  = st_y1[qq] * (1.0f / 256.0f);                      \
                float vary = st_y2[qq] * (1.0f / 256.0f) - muy * muy;          \
                sAlpha[ry] = tanhf(rsqrtf(vary + 1e-5f) *                      \
                                   (st_y3[qq] - muy * Sgw) + Sbw);             \
            }                                                                  \
        }                                                                      \
    }

    // ---- GEMM + stats + C for batch A ----
    {
        unsigned long long acc2[8][2];
#pragma unroll
        for (int r = 0; r < 8; r++) { acc2[r][0] = 0ull; acc2[r][1] = 0ull; }
        STAT_CLEAR();
        DO_GEMM(xbA, ybA, acc2);
        STAT_WRITE(0);
        __syncthreads();   // sScale[0..127] visible; staging reads done
        const float sj0 = sScale[64 + c0] * 10.0f;
        const float sj1 = sScale[64 + c1] * 10.0f;
#pragma unroll
        for (int r = 0; r < 8; r++) {
            float si = sScale[w8 + r];
            sCA[(w8 + r) * NP + c0] = pairsum(acc2[r][0]) * si * sj0;
            sCA[(w8 + r) * NP + c1] = pairsum(acc2[r][1]) * si * sj1;
        }
    }
    // ---- GEMM + stats + C for batch B ----
    {
        unsigned long long acc2[8][2];
#pragma unroll
        for (int r = 0; r < 8; r++) { acc2[r][0] = 0ull; acc2[r][1] = 0ull; }
        STAT_CLEAR();
        DO_GEMM(xbB, ybB, acc2);
        STAT_WRITE(128);
        __syncthreads();   // sScale[128..255] visible; staging reads done
        const float sj0 = sScale[192 + c0] * 10.0f;
        const float sj1 = sScale[192 + c1] * 10.0f;
#pragma unroll
        for (int r = 0; r < 8; r++) {
            float si  = sScale[128 + w8 + r];
            float cv0 = pairsum(acc2[r][0]) * si * sj0;
            float cv1 = pairsum(acc2[r][1]) * si * sj1;
            sCB[(w8 + r) * NP + c0] = cv0;
            sCB[(w8 + r) * NP + c1] = cv1;
            kreg2B[r] = pack2(__expf(cv0), __expf(cv1));
        }
    }
    // kreg2A regenerated from C_A (cells this thread wrote)
#pragma unroll
    for (int r = 0; r < 8; r++)
        kreg2A[r] = pack2(__expf(sCA[(w8 + r) * NP + c0]),
                          __expf(sCA[(w8 + r) * NP + c1]));

    // ---- dustbins, corners, b init ----
    if (t < 64) {
        float cx = 10.0f * sAlpha[t];
        sCA[t * NP + 64] = cx;  sKdbColA[t] = __expf(cx);
        float cy = 10.0f * sAlpha[64 + t];
        sCA[64 * NP + t] = cy;  sKdbRowA[t] = __expf(cy);
        float dx = 10.0f * sAlpha[128 + t];
        sCB[t * NP + 64] = dx;  sKdbColB[t] = __expf(dx);
        float dy = 10.0f * sAlpha[192 + t];
        sCB[64 * NP + t] = dy;  sKdbRowB[t] = __expf(dy);
    }
    if (t == 0) {
        sCA[64 * NP + 64] = -1000.0f;  sKdbRowA[64] = 0.0f;  sKdbColA[64] = 0.0f;
        sCB[64 * NP + 64] = -1000.0f;  sKdbRowB[64] = 0.0f;  sKdbColB[64] = 0.0f;
        sA64A = 0.0f; sA64B = 0.0f;
    }
    if (t < NP) sBvA[t] = 1.0f;
    if (t >= 128 && t < 128 + NP) sBvB[t - 128] = 1.0f;
    __syncthreads();

    // ---- Sinkhorn: 20 iterations, 2 barriers/iter ----
    float rcpA = 0.f, rcpB = 0.f;
    const float kColA = sKdbColA[w8 + rl];
    const float kColB = sKdbColB[w8 + rl];

    for (int it = 0; it < 20; it++) {
        float bA0 = sBvA[c0], bA1 = sBvA[c1], bA64 = sBvA[64];
        float bB0 = sBvB[c0], bB1 = sBvB[c1], bB64 = sBvB[64];
        // u-phase row sums
        {
            unsigned long long b2 = pack2(bA0, bA1);
            float s[8];
#pragma unroll
            for (int r = 0; r < 8; r++) s[r] = pairsum(fmul2(kreg2A[r], b2));
            float z = collapse8(s, lane);
            z = fmaf(kColA, bA64, z);
            rcpA = __fdividef(MU_IN, z);
        }
        {
            unsigned long long b2 = pack2(bB0, bB1);
            float s[8];
#pragma unroll
            for (int r = 0; r < 8; r++) s[r] = pairsum(fmul2(kreg2B[r], b2));
            float z = collapse8(s, lane);
            z = fmaf(kColB, bB64, z);
            rcpB = __fdividef(MU_IN, z);
        }
        // dustbin rows: dedicated warps
        if (wid == 3) {
            float pdb = fmaf(sKdbRowA[c0], bA0, sKdbRowA[c1] * bA1);
            pdb = warp_sum(pdb);
            if (lane == 0) sA64A = __fdividef(MU_DB, pdb);
        }
        if (wid == 7) {
            float pdb = fmaf(sKdbRowB[c0], bB0, sKdbRowB[c1] * bB1);
            pdb = warp_sum(pdb);
            if (lane == 0) sA64B = __fdividef(MU_DB, pdb);
        }
        // v-phase partials
        {
            unsigned long long q2 = 0ull;
            float qdb = 0.f;
#pragma unroll
            for (int r = 0; r < 8; r++) {
                float ar = __shfl_sync(0xffffffffu, rcpA, r * 4);
                q2  = ffma2(kreg2A[r], pack2(ar, ar), q2);
                qdb = fmaf(sKdbColA[w8 + r], ar, qdb);
            }
            float q0, q1; unpack2(q2, q0, q1);
            sPartA[wid * 66 + c0] = q0;
            sPartA[wid * 66 + c1] = q1;
            if (lane == 0) sPartA[wid * 66 + 64] = qdb;
        }
        {
            unsigned long long q2 = 0ull;
            float qdb = 0.f;
#pragma unroll
            for (int r = 0; r < 8; r++) {
                float ar = __shfl_sync(0xffffffffu, rcpB, r * 4);
                q2  = ffma2(kreg2B[r], pack2(ar, ar), q2);
                qdb = fmaf(sKdbColB[w8 + r], ar, qdb);
            }
            float q0, q1; unpack2(q2, q0, q1);
            sPartB[wid * 66 + c0] = q0;
            sPartB[wid * 66 + c1] = q1;
            if (lane == 0) sPartB[wid * 66 + 64] = qdb;
        }
        __syncthreads();
        // b update: warps 0-2 batch A, warps 4-6 batch B
        if (t < NP) {
            float cs = 0.f;
#pragma unroll
            for (int w = 0; w < 8; w++) cs += sPartA[w * 66 + t];
            sBvA[t] = (t < 64) ? __fdividef(MU_IN, fmaf(sKdbRowA[t], sA64A, cs))
                               : __fdividef(MU_DB, cs);
        }
        if (t >= 128 && t < 128 + NP) {
            int tt = t - 128;
            float cs = 0.f;
#pragma unroll
            for (int w = 0; w < 8; w++) cs += sPartB[w * 66 + tt];
            sBvB[tt] = (tt < 64) ? __fdividef(MU_IN, fmaf(sKdbRowB[tt], sA64B, cs))
                                 : __fdividef(MU_DB, cs);
        }
        __syncthreads();
    }

    // ---- Epilogue ----
    if ((lane & 3) == 0) { sAfinA[w8 + rl] = rcpA; sAfinB[w8 + rl] = rcpB; }
    if (t == 0) { sAfinA[64] = sA64A; sAfinB[64] = sA64B; }
    __syncthreads();
    if (t < NP) { sLaA[t] = __logf(sAfinA[t]); sLbA[t] = __logf(sBvA[t]); }
    if (t >= 128 && t < 128 + NP) {
        int tt = t - 128;
        sLaB[tt] = __logf(sAfinB[tt]); sLbB[tt] = __logf(sBvB[tt]);
    }
    __syncthreads();

    float* omA = out_match + (size_t)bA * (NP * NP);
    float* omB = out_match + (size_t)bB * (NP * NP);
    for (int i = wid; i < NP; i += 8) {
        float laA = sLaA[i] + LOG128;
        float laB = sLaB[i] + LOG128;
        const float* CiA = sCA + i * NP;
        const float* CiB = sCB + i * NP;
        float* oA = omA + i * NP;
        float* oB = omB + i * NP;
        for (int j = lane; j < NP; j += 32) {
            oA[j] = CiA[j] + laA + sLbA[j];
            oB[j] = CiB[j] + laB + sLbB[j];
        }
    }

    if (write_score) {
        float pA = 0.f, pB = 0.f;
        float bbA0 = sBvA[c0], bbA1 = sBvA[c1];
        float bbB0 = sBvB[c0], bbB1 = sBvB[c1];
#pragma unroll
        for (int r = 0; r < 8; r++) {
            float arA = __shfl_sync(0xffffffffu, rcpA, r * 4);
            float arB = __shfl_sync(0xffffffffu, rcpB, r * 4);
            float k0, k1;
            unpack2(kreg2A[r], k0, k1);
            pA += arA * (k0 * sCA[(w8 + r) * NP + c0] * bbA0 +
                         k1 * sCA[(w8 + r) * NP + c1] * bbA1);
            unpack2(kreg2B[r], k0, k1);
            pB += arB * (k0 * sCB[(w8 + r) * NP + c0] * bbB0 +
                         k1 * sCB[(w8 + r) * NP + c1] * bbB1);
        }
        pA = warp_sum(pA);
        pB = warp_sum(pB);
        if (lane == 0) { sRed[wid] = pA; sRed[8 + wid] = pB; }
        __syncthreads();
        if (t == 0) {
            float sa = 0.f, sb = 0.f;
#pragma unroll
            for (int i = 0; i < 8; i++) { sa += sRed[i]; sb += sRed[8 + i]; }
            out_score[bA] = sa * 128.0f;
            out_score[bB] = sb * 128.0f;
        }
    }
#undef DO_GEMM
#undef STAT_ACC
#undef STAT_CLEAR
#undef STAT_WRITE
}

extern "C" void kernel_launch(void* const* d_in, const int* in_sizes, int n_in,
                              void* d_out, int out_size) {
    const float* x     = (const float*)d_in[0];
    const float* y     = (const float*)d_in[1];
    const float* gamma = (const float*)d_in[2];
    const float* beta  = (const float*)d_in[3];
    const float* wdb   = (const float*)d_in[4];
    const float* bdb   = (const float*)d_in[5];

    int B = in_sizes[0] / (NN * H);                 // 4096 (even)
    size_t msz = (size_t)B * NP * NP;
    float* out_match = (float*)d_out;
    float* out_score = (float*)d_out + msz;
    int write_score = ((size_t)out_size >= msz + (size_t)B) ? 1 : 0;

    sinkhorn_fused_kernel<<<B / 2, 256>>>(x, y, gamma, beta, wdb, bdb,
                                          out_match, out_score, write_score);
}

// round 7
// speedup vs baseline: 1.2032x; 1.0162x over previous
#include <cuda_runtime.h>

// SinkhornScorer fused kernel for GB300 (sm_103a).
// R7: half-warp GEMM tiling (4 rows x 4 cols per thread; lanes 0-15 rows
// w8..w8+3, lanes 16-31 rows w8+4..w8+7, each lane cols {li, li+16, li+32,
// li+48}). Cuts GEMM smem wavefronts 16 -> 12 per k4 per warp. Sinkhorn row
// reduction now 5 shfls over 16 lanes. Stats stay fused in staging loads;
// chunk gmem loads issued before the staging barrier (no prefetch regs).

namespace {
constexpr int H   = 256;
constexpr int NN  = 64;
constexpr int NP  = 65;
constexpr float LOG128 = 4.852030263919617f;
constexpr float MU_IN  = 0.0078125f;   // 1/128
constexpr float MU_DB  = 0.5f;         // 64/128

__device__ __forceinline__ float warp_sum(float v) {
#pragma unroll
    for (int o = 16; o; o >>= 1) v += __shfl_xor_sync(0xffffffffu, v, o);
    return v;
}
__device__ __forceinline__ unsigned long long ffma2(
    unsigned long long a, unsigned long long b, unsigned long long c) {
    unsigned long long d;
    asm("fma.rn.f32x2 %0, %1, %2, %3;" : "=l"(d) : "l"(a), "l"(b), "l"(c));
    return d;
}
__device__ __forceinline__ unsigned long long fmul2(
    unsigned long long a, unsigned long long b) {
    unsigned long long d;
    asm("mul.rn.f32x2 %0, %1, %2;" : "=l"(d) : "l"(a), "l"(b));
    return d;
}
__device__ __forceinline__ unsigned long long pack2(float lo, float hi) {
    unsigned long long d;
    asm("mov.b64 %0, {%1, %2};" : "=l"(d) : "f"(lo), "f"(hi));
    return d;
}
__device__ __forceinline__ void unpack2(unsigned long long v, float& lo, float& hi) {
    asm("mov.b64 {%0, %1}, %2;" : "=f"(lo), "=f"(hi) : "l"(v));
}
__device__ __forceinline__ float pairsum(unsigned long long v) {
    float lo, hi; unpack2(v, lo, hi); return lo + hi;
}

// Fold 4 per-lane row partials over a 16-lane half-warp (offsets 8,4,2,1).
// On return every lane holds the full sum of row rown = 2*((li>>3)&1)+((li>>2)&1).
__device__ __forceinline__ float collapse4h(const float* s, int li) {
    const bool q8 = (li & 8) != 0;
    const bool q4 = (li & 4) != 0;
    float t0 = __shfl_xor_sync(0xffffffffu, q8 ? s[0] : s[2], 8);
    float t1 = __shfl_xor_sync(0xffffffffu, q8 ? s[1] : s[3], 8);
    float u0 = (q8 ? s[2] : s[0]) + t0;
    float u1 = (q8 ? s[3] : s[1]) + t1;
    float t2 = __shfl_xor_sync(0xffffffffu, q4 ? u0 : u1, 4);
    float v = (q4 ? u1 : u0) + t2;
    v += __shfl_xor_sync(0xffffffffu, v, 2);
    v += __shfl_xor_sync(0xffffffffu, v, 1);
    return v;
}
}  // namespace

__global__ void __launch_bounds__(256, 3) sinkhorn_fused_kernel(
    const float* __restrict__ x, const float* __restrict__ y,
    const float* __restrict__ gamma, const float* __restrict__ beta,
    const float* __restrict__ wdb, const float* __restrict__ bdb,
    float* __restrict__ out_match, float* __restrict__ out_score,
    int write_score)
{
    const int bA   = blockIdx.x * 2;
    const int bB   = bA + 1;
    const int t    = threadIdx.x;
    const int lane = t & 31;
    const int wid  = t >> 5;
    const int w8   = wid * 8;
    const int h    = lane >> 4;        // half-warp id
    const int li   = lane & 15;        // lane within half
    const int rown = 2 * ((li >> 3) & 1) + ((li >> 2) & 1);
    const int Rown = w8 + 4 * h + rown;

    __shared__ __align__(16) float sCA[4240];   // C for batch A
    __shared__ __align__(16) float sCB[4240];   // C for batch B; staging overlay
    __shared__ __align__(16) float sGw[256];
    __shared__ float sScale[256];               // xA|yA|xB|yB
    __shared__ float sAlpha[256];
    __shared__ float sBvA[NP], sBvB[NP];
    __shared__ float sKdbRowA[NP], sKdbRowB[NP], sKdbColA[NP], sKdbColB[NP];
    __shared__ float sPartA[8 * 66], sPartB[8 * 66];
    __shared__ float sAfinA[NP], sAfinB[NP], sLaA[NP], sLaB[NP], sLbA[NP], sLbB[NP];
    __shared__ float sRed[16];
    __shared__ float sSgw, sSbw, sA64A, sA64B;

    // ---- constants: gw = gamma*w; S_gw = sum gw; S_bw = sum beta*w + b_db ----
    {
        float gwv = gamma[t] * wdb[t];
        float bwv = beta[t] * wdb[t];
        sGw[t] = gwv;
        gwv = warp_sum(gwv);
        bwv = warp_sum(bwv);
        if (lane == 0) { sRed[wid] = gwv; sRed[8 + wid] = bwv; }
    }
    __syncthreads();
    if (t == 0) {
        float a = 0.f, c = 0.f;
#pragma unroll
        for (int i = 0; i < 8; i++) { a += sRed[i]; c += sRed[8 + i]; }
        sSgw = a;
        sSbw = c + bdb[0];
    }
    __syncthreads();

    const float* xbA = x + (size_t)bA * NN * H;
    const float* ybA = y + (size_t)bA * NN * H;
    const float* xbB = x + (size_t)bB * NN * H;
    const float* ybB = y + (size_t)bB * NN * H;

    // Staging overlays sCB (4096 floats used)
    float4* xs4 = (float4*)sCB;            // [64][8] float4, swizzled
    float4* ys4 = ((float4*)sCB) + 512;
    const ulonglong2* xs2 = (const ulonglong2*)xs4;
    const ulonglong2* ys2 = (const ulonglong2*)ys4;
    const float4* gw4 = (const float4*)sGw;

    unsigned long long kreg2A[4][2], kreg2B[4][2];

    // per-thread row-stat accumulators (stages rows t>>3 and t>>3+32 of x, y)
    float st_x1[2], st_x2[2], st_x3[2], st_y1[2], st_y2[2], st_y3[2];

#define STAT_CLEAR()                                                           \
    _Pragma("unroll")                                                          \
    for (int qq = 0; qq < 2; qq++) {                                           \
        st_x1[qq] = 0.f; st_x2[qq] = 0.f; st_x3[qq] = 0.f;                     \
        st_y1[qq] = 0.f; st_y2[qq] = 0.f; st_y3[qq] = 0.f;                     \
    }

#define STAT_ACC(GQ)                                                           \
    _Pragma("unroll")                                                          \
    for (int qq = 0; qq < 2; qq++) {                                           \
        float4 v = px[qq];                                                     \
        st_x1[qq] += (v.x + v.y) + (v.z + v.w);                                \
        st_x2[qq] += v.x * v.x + v.y * v.y + v.z * v.z + v.w * v.w;            \
        st_x3[qq] += v.x * (GQ).x + v.y * (GQ).y + v.z * (GQ).z + v.w * (GQ).w;\
        float4 u = py[qq];                                                     \
        st_y1[qq] += (u.x + u.y) + (u.z + u.w);                                \
        st_y2[qq] += u.x * u.x + u.y * u.y + u.z * u.z + u.w * u.w;            \
        st_y3[qq] += u.x * (GQ).x + u.y * (GQ).y + u.z * (GQ).z + u.w * (GQ).w;\
    }

    // GEMM: acc2[r][c] accumulates (row w8+4h+r) x (col 16c+li), k-paired f32x2.
#define DO_GEMM(XG, YG, ACC)                                                   \
    {                                                                          \
        const float4* xg = (const float4*)(XG);                                \
        const float4* yg = (const float4*)(YG);                                \
        const int srow = t >> 3, sc4 = t & 7;                                  \
        for (int kc = 0; kc < 8; kc++) {                                       \
            float4 px[2], py[2];                                               \
            int col = kc * 8 + sc4;                                            \
            px[0] = xg[srow * 64 + col];                                       \
            px[1] = xg[(srow + 32) * 64 + col];                                \
            py[0] = yg[srow * 64 + col];                                       \
            py[1] = yg[(srow + 32) * 64 + col];                                \
            __syncthreads();                                                   \
            {                                                                  \
                int sw0 = sc4 ^ (srow & 7);                                    \
                xs4[srow * 8 + sw0] = px[0];                                   \
                ys4[srow * 8 + sw0] = py[0];                                   \
                xs4[(srow + 32) * 8 + sw0] = px[1];                            \
                ys4[(srow + 32) * 8 + sw0] = py[1];                            \
            }                                                                  \
            {                                                                  \
                float4 gq = gw4[col];                                          \
                STAT_ACC(gq);                                                  \
            }                                                                  \
            __syncthreads();                                                   \
            _Pragma("unroll")                                                  \
            for (int k4 = 0; k4 < 8; k4++) {                                   \
                int ysw = k4 ^ (li & 7);                                       \
                ulonglong2 yv0 = ys2[li * 8 + ysw];                            \
                ulonglong2 yv1 = ys2[(li + 16) * 8 + ysw];                     \
                ulonglong2 yv2 = ys2[(li + 32) * 8 + ysw];                     \
                ulonglong2 yv3 = ys2[(li + 48) * 8 + ysw];                     \
                _Pragma("unroll")                                              \
                for (int r = 0; r < 4; r++) {                                  \
                    int row = w8 + 4 * h + r;                                  \
                    ulonglong2 xv = xs2[row * 8 + (k4 ^ ((4 * h + r) & 7))];   \
                    ACC[r][0] = ffma2(xv.x, yv0.x, ACC[r][0]);                 \
                    ACC[r][0] = ffma2(xv.y, yv0.y, ACC[r][0]);                 \
                    ACC[r][1] = ffma2(xv.x, yv1.x, ACC[r][1]);                 \
                    ACC[r][1] = ffma2(xv.y, yv1.y, ACC[r][1]);                 \
                    ACC[r][2] = ffma2(xv.x, yv2.x, ACC[r][2]);                 \
                    ACC[r][2] = ffma2(xv.y, yv2.y, ACC[r][2]);                 \
                    ACC[r][3] = ffma2(xv.x, yv3.x, ACC[r][3]);                 \
                    ACC[r][3] = ffma2(xv.y, yv3.y, ACC[r][3]);                 \
                }                                                              \
            }                                                                  \
        }                                                                      \
    }

#define STAT_WRITE(BASE)                                                       \
    {                                                                          \
        _Pragma("unroll")                                                      \
        for (int o = 1; o <= 4; o <<= 1) {                                     \
            _Pragma("unroll")                                                  \
            for (int qq = 0; qq < 2; qq++) {                                   \
                st_x1[qq] += __shfl_xor_sync(0xffffffffu, st_x1[qq], o);       \
                st_x2[qq] += __shfl_xor_sync(0xffffffffu, st_x2[qq], o);       \
                st_x3[qq] += __shfl_xor_sync(0xffffffffu, st_x3[qq], o);       \
                st_y1[qq] += __shfl_xor_sync(0xffffffffu, st_y1[qq], o);       \
                st_y2[qq] += __shfl_xor_sync(0xffffffffu, st_y2[qq], o);       \
                st_y3[qq] += __shfl_xor_sync(0xffffffffu, st_y3[qq], o);       \
            }                                                                  \
        }                                                                      \
        if ((lane & 7) == 0) {                                                 \
            int row = wid * 4 + (lane >> 3);                                   \
            float Sgw = sSgw, Sbw = sSbw;                                      \
            _Pragma("unroll")                                                  \
            for (int qq = 0; qq < 2; qq++) {                                   \
                int rx = (BASE) + row + 32 * qq;                               \
                sScale[rx] = 1.0f / fmaxf(sqrtf(st_x2[qq]), 1e-12f);           \
                float mu  = st_x1[qq] * (1.0f / 256.0f);                       \
                float var = st_x2[qq] * (1.0f / 256.0f) - mu * mu;             \
                sAlpha[rx] = tanhf(rsqrtf(var + 1e-5f) *                       \
                                   (st_x3[qq] - mu * Sgw) + Sbw);              \
                int ry = (BASE) + 64 + row + 32 * qq;                          \
                sScale[ry] = 1.0f / fmaxf(sqrtf(st_y2[qq]), 1e-12f);           \
                float muy  = st_y1[qq] * (1.0f / 256.0f);                      \
                float vary = st_y2[qq] * (1.0f / 256.0f) - muy * muy;          \
                sAlpha[ry] = tanhf(rsqrtf(vary + 1e-5f) *                      \
                                   (st_y3[qq] - muy * Sgw) + Sbw);             \
            }                                                                  \
        }                                                                      \
    }

    // ---- GEMM + stats + C for batch A ----
    {
        unsigned long long acc2[4][4];
#pragma unroll
        for (int r = 0; r < 4; r++)
#pragma unroll
            for (int c = 0; c < 4; c++) acc2[r][c] = 0ull;
        STAT_CLEAR();
        DO_GEMM(xbA, ybA, acc2);
        STAT_WRITE(0);
        __syncthreads();   // sScale[0..127] visible; staging reads done
#pragma unroll
        for (int r = 0; r < 4; r++) {
            float si = sScale[w8 + 4 * h + r];
#pragma unroll
            for (int c = 0; c < 4; c++) {
                int col = 16 * c + li;
                sCA[(w8 + 4 * h + r) * NP + col] =
                    pairsum(acc2[r][c]) * si * (sScale[64 + col] * 10.0f);
            }
        }
    }
    // ---- GEMM + stats + C for batch B ----
    {
        unsigned long long acc2[4][4];
#pragma unroll
        for (int r = 0; r < 4; r++)
#pragma unroll
            for (int c = 0; c < 4; c++) acc2[r][c] = 0ull;
        STAT_CLEAR();
        DO_GEMM(xbB, ybB, acc2);
        STAT_WRITE(128);
        __syncthreads();   // sScale[128..255] visible; staging reads done
#pragma unroll
        for (int r = 0; r < 4; r++) {
            float si = sScale[128 + w8 + 4 * h + r];
            float cv[4];
#pragma unroll
            for (int c = 0; c < 4; c++) {
                int col = 16 * c + li;
                cv[c] = pairsum(acc2[r][c]) * si * (sScale[192 + col] * 10.0f);
                sCB[(w8 + 4 * h + r) * NP + col] = cv[c];
            }
            kreg2B[r][0] = pack2(__expf(cv[0]), __expf(cv[1]));
            kreg2B[r][1] = pack2(__expf(cv[2]), __expf(cv[3]));
        }
    }
    // kreg2A regenerated from C_A (cells this thread wrote)
#pragma unroll
    for (int r = 0; r < 4; r++) {
        const float* Crow = sCA + (w8 + 4 * h + r) * NP;
        kreg2A[r][0] = pack2(__expf(Crow[li]), __expf(Crow[li + 16]));
        kreg2A[r][1] = pack2(__expf(Crow[li + 32]), __expf(Crow[li + 48]));
    }

    // ---- dustbins, corners, b init ----
    if (t < 64) {
        float cx = 10.0f * sAlpha[t];
        sCA[t * NP + 64] = cx;  sKdbColA[t] = __expf(cx);
        float cy = 10.0f * sAlpha[64 + t];
        sCA[64 * NP + t] = cy;  sKdbRowA[t] = __expf(cy);
        float dx = 10.0f * sAlpha[128 + t];
        sCB[t * NP + 64] = dx;  sKdbColB[t] = __expf(dx);
        float dy = 10.0f * sAlpha[192 + t];
        sCB[64 * NP + t] = dy;  sKdbRowB[t] = __expf(dy);
    }
    if (t == 0) {
        sCA[64 * NP + 64] = -1000.0f;  sKdbRowA[64] = 0.0f;  sKdbColA[64] = 0.0f;
        sCB[64 * NP + 64] = -1000.0f;  sKdbRowB[64] = 0.0f;  sKdbColB[64] = 0.0f;
        sA64A = 0.0f; sA64B = 0.0f;
    }
    if (t < NP) sBvA[t] = 1.0f;
    if (t >= 128 && t < 128 + NP) sBvB[t - 128] = 1.0f;
    __syncthreads();

    // ---- Sinkhorn: 20 iterations, 2 barriers/iter ----
    float rcpA = 0.f, rcpB = 0.f;
    const float kColOwnA = sKdbColA[Rown];
    const float kColOwnB = sKdbColB[Rown];
    float kcA[4], kcB[4];
#pragma unroll
    for (int r = 0; r < 4; r++) {
        kcA[r] = sKdbColA[w8 + 4 * h + r];
        kcB[r] = sKdbColB[w8 + 4 * h + r];
    }
    const int src0 = 16 * h;   // shfl src base for a-broadcast

    for (int it = 0; it < 20; it++) {
        // ---- u-phase row sums ----
        float bA0 = sBvA[li], bA1 = sBvA[li + 16],
              bA2 = sBvA[li + 32], bA3 = sBvA[li + 48], bA64 = sBvA[64];
        float bB0 = sBvB[li], bB1 = sBvB[li + 16],
              bB2 = sBvB[li + 32], bB3 = sBvB[li + 48], bB64 = sBvB[64];
        {
            unsigned long long b01 = pack2(bA0, bA1), b23 = pack2(bA2, bA3);
            float s[4];
#pragma unroll
            for (int r = 0; r < 4; r++)
                s[r] = pairsum(fmul2(kreg2A[r][0], b01)) +
                       pairsum(fmul2(kreg2A[r][1], b23));
            float z = collapse4h(s, li);
            z = fmaf(kColOwnA, bA64, z);
            rcpA = __fdividef(MU_IN, z);
        }
        {
            unsigned long long b01 = pack2(bB0, bB1), b23 = pack2(bB2, bB3);
            float s[4];
#pragma unroll
            for (int r = 0; r < 4; r++)
                s[r] = pairsum(fmul2(kreg2B[r][0], b01)) +
                       pairsum(fmul2(kreg2B[r][1], b23));
            float z = collapse4h(s, li);
            z = fmaf(kColOwnB, bB64, z);
            rcpB = __fdividef(MU_IN, z);
        }
        // dustbin rows: dedicated warps
        if (wid == 3) {
            float pdb = fmaf(sKdbRowA[lane], sBvA[lane],
                             sKdbRowA[lane + 32] * sBvA[lane + 32]);
            pdb = warp_sum(pdb);
            if (lane == 0) sA64A = __fdividef(MU_DB, pdb);
        }
        if (wid == 7) {
            float pdb = fmaf(sKdbRowB[lane], sBvB[lane],
                             sKdbRowB[lane + 32] * sBvB[lane + 32]);
            pdb = warp_sum(pdb);
            if (lane == 0) sA64B = __fdividef(MU_DB, pdb);
        }
        // ---- v-phase partials ----
        {
            unsigned long long q01 = 0ull, q23 = 0ull;
            float qdb = 0.f;
#pragma unroll
            for (int r = 0; r < 4; r++) {
                float ar = __shfl_sync(0xffffffffu, rcpA,
                                       src0 + 8 * (r >> 1) + 4 * (r & 1));
                unsigned long long a2 = pack2(ar, ar);
                q01 = ffma2(kreg2A[r][0], a2, q01);
                q23 = ffma2(kreg2A[r][1], a2, q23);
                qdb = fmaf(kcA[r], ar, qdb);
            }
            float q0, q1, q2, q3;
            unpack2(q01, q0, q1);
            unpack2(q23, q2, q3);
            q0 += __shfl_xor_sync(0xffffffffu, q0, 16);
            q1 += __shfl_xor_sync(0xffffffffu, q1, 16);
            q2 += __shfl_xor_sync(0xffffffffu, q2, 16);
            q3 += __shfl_xor_sync(0xffffffffu, q3, 16);
            qdb += __shfl_xor_sync(0xffffffffu, qdb, 16);
            if (h == 0) {
                float* P = sPartA + wid * 66;
                P[li] = q0; P[li + 16] = q1; P[li + 32] = q2; P[li + 48] = q3;
                if (li == 0) P[64] = qdb;
            }
        }
        {
            unsigned long long q01 = 0ull, q23 = 0ull;
            float qdb = 0.f;
#pragma unroll
            for (int r = 0; r < 4; r++) {
                float ar = __shfl_sync(0xffffffffu, rcpB,
                                       src0 + 8 * (r >> 1) + 4 * (r & 1));
                unsigned long long a2 = pack2(ar, ar);
                q01 = ffma2(kreg2B[r][0], a2, q01);
                q23 = ffma2(kreg2B[r][1], a2, q23);
                qdb = fmaf(kcB[r], ar, qdb);
            }
            float q0, q1, q2, q3;
            unpack2(q01, q0, q1);
            unpack2(q23, q2, q3);
            q0 += __shfl_xor_sync(0xffffffffu, q0, 16);
            q1 += __shfl_xor_sync(0xffffffffu, q1, 16);
            q2 += __shfl_xor_sync(0xffffffffu, q2, 16);
            q3 += __shfl_xor_sync(0xffffffffu, q3, 16);
            qdb += __shfl_xor_sync(0xffffffffu, qdb, 16);
            if (h == 0) {
                float* P = sPartB + wid * 66;
                P[li] = q0; P[li + 16] = q1; P[li + 32] = q2; P[li + 48] = q3;
                if (li == 0) P[64] = qdb;
            }
        }
        __syncthreads();
        // ---- b update ----
        if (t < NP) {
            float cs = 0.f;
#pragma unroll
            for (int w = 0; w < 8; w++) cs += sPartA[w * 66 + t];
            sBvA[t] = (t < 64) ? __fdividef(MU_IN, fmaf(sKdbRowA[t], sA64A, cs))
                               : __fdividef(MU_DB, cs);
        }
        if (t >= 128 && t < 128 + NP) {
            int tt = t - 128;
            float cs = 0.f;
#pragma unroll
            for (int w = 0; w < 8; w++) cs += sPartB[w * 66 + tt];
            sBvB[tt] = (tt < 64) ? __fdividef(MU_IN, fmaf(sKdbRowB[tt], sA64B, cs))
                                 : __fdividef(MU_DB, cs);
        }
        __syncthreads();
    }

    // ---- Epilogue ----
    if ((li & 3) == 0) { sAfinA[Rown] = rcpA; sAfinB[Rown] = rcpB; }
    if (t == 0) { sAfinA[64] = sA64A; sAfinB[64] = sA64B; }
    __syncthreads();
    if (t < NP) { sLaA[t] = __logf(sAfinA[t]); sLbA[t] = __logf(sBvA[t]); }
    if (t >= 128 && t < 128 + NP) {
        int tt = t - 128;
        sLaB[tt] = __logf(sAfinB[tt]); sLbB[tt] = __logf(sBvB[tt]);
    }
    __syncthreads();

    float* omA = out_match + (size_t)bA * (NP * NP);
    float* omB = out_match + (size_t)bB * (NP * NP);
    for (int i = wid; i < NP; i += 8) {
        float laA = sLaA[i] + LOG128;
        float laB = sLaB[i] + LOG128;
        const float* CiA = sCA + i * NP;
        const float* CiB = sCB + i * NP;
        float* oA = omA + i * NP;
        float* oB = omB + i * NP;
        for (int j = lane; j < NP; j += 32) {
            oA[j] = CiA[j] + laA + sLbA[j];
            oB[j] = CiB[j] + laB + sLbB[j];
        }
    }

    if (write_score) {
        float pA = 0.f, pB = 0.f;
        float bbA[4] = { sBvA[li], sBvA[li + 16], sBvA[li + 32], sBvA[li + 48] };
        float bbB[4] = { sBvB[li], sBvB[li + 16], sBvB[li + 32], sBvB[li + 48] };
#pragma unroll
        for (int r = 0; r < 4; r++) {
            float arA = __shfl_sync(0xffffffffu, rcpA,
                                    src0 + 8 * (r >> 1) + 4 * (r & 1));
            float arB = __shfl_sync(0xffffffffu, rcpB,
                                    src0 + 8 * (r >> 1) + 4 * (r & 1));
            const float* CrA = sCA + (w8 + 4 * h + r) * NP;
            const float* CrB = sCB + (w8 + 4 * h + r) * NP;
            float kA0, kA1, kA2, kA3, kB0, kB1, kB2, kB3;
            unpack2(kreg2A[r][0], kA0, kA1);
            unpack2(kreg2A[r][1], kA2, kA3);
            unpack2(kreg2B[r][0], kB0, kB1);
            unpack2(kreg2B[r][1], kB2, kB3);
            pA += arA * (kA0 * CrA[li] * bbA[0] + kA1 * CrA[li + 16] * bbA[1] +
                         kA2 * CrA[li + 32] * bbA[2] + kA3 * CrA[li + 48] * bbA[3]);
            pB += arB * (kB0 * CrB[li] * bbB[0] + kB1 * CrB[li + 16] * bbB[1] +
                         kB2 * CrB[li + 32] * bbB[2] + kB3 * CrB[li + 48] * bbB[3]);
        }
        pA = warp_sum(pA);
        pB = warp_sum(pB);
        if (lane == 0) { sRed[wid] = pA; sRed[8 + wid] = pB; }
        __syncthreads();
        if (t == 0) {
            float sa = 0.f, sb = 0.f;
#pragma unroll
            for (int i = 0; i < 8; i++) { sa += sRed[i]; sb += sRed[8 + i]; }
            out_score[bA] = sa * 128.0f;
            out_score[bB] = sb * 128.0f;
        }
    }
#undef DO_GEMM
#undef STAT_ACC
#undef STAT_CLEAR
#undef STAT_WRITE
}

extern "C" void kernel_launch(void* const* d_in, const int* in_sizes, int n_in,
                              void* d_out, int out_size) {
    const float* x     = (const float*)d_in[0];
    const float* y     = (const float*)d_in[1];
    const float* gamma = (const float*)d_in[2];
    const float* beta  = (const float*)d_in[3];
    const float* wdb   = (const float*)d_in[4];
    const float* bdb   = (const float*)d_in[5];

    int B = in_sizes[0] / (NN * H);                 // 4096 (even)
    size_t msz = (size_t)B * NP * NP;
    float* out_match = (float*)d_out;
    float* out_score = (float*)d_out + msz;
    int write_score = ((size_t)out_size >= msz + (size_t)B) ? 1 : 0;

    sinkhorn_fused_kernel<<<B / 2, 256>>>(x, y, gamma, beta, wdb, bdb,
                                          out_match, out_score, write_score);
}